// round 11
// baseline (speedup 1.0000x reference)
#include <cuda_runtime.h>
#include <cuda_fp16.h>
#include <cstdint>
#include <math.h>

#define BATCH 4
#define NH 32
#define SEQQ 512
#define HD 128
#define NMEM 4096
#define MAXB 4
#define BQ 128
#define BK 64
#define NTHREADS 256

// row = 128 halves = 256 bytes = 16 units of 16B
#define ROWB 256
#define ONES_H2 0x3C003C00u

// ---------------- device scratch (allocation-free) ----------------
__device__ __half g_Qh[BATCH * NH * SEQQ * HD];              // roped, *log2e/sqrt(d), fp16
__device__ __half g_Kh[BATCH * NH * SEQQ * HD];              // roped K, fp16 natural
__device__ __half g_Vh[BATCH * NH * SEQQ * HD];              // V, fp16 natural
__device__ __half g_KmemH[(size_t)BATCH * NH * NMEM * HD];   // mem K prefix, head-major fp16
__device__ __half g_VmemH[(size_t)BATCH * NH * NMEM * HD];   // mem V prefix, head-major fp16
__device__ float g_cos[SEQQ * (HD / 2)];
__device__ float g_sin[SEQQ * (HD / 2)];

// ---------------- helpers ----------------
__device__ __forceinline__ uint32_t s2u(const void* p) {
    uint32_t a;
    asm("{ .reg .u64 t; cvta.to.shared.u64 t, %1; cvt.u32.u64 %0, t; }" : "=r"(a) : "l"(p));
    return a;
}
__device__ __forceinline__ uint32_t pack_h2(float lo, float hi) {
    uint32_t r;
    asm("cvt.rn.f16x2.f32 %0, %1, %2;" : "=r"(r) : "f"(hi), "f"(lo));  // {hi:upper, lo:lower}
    return r;
}
__device__ __forceinline__ float ex2f(float x) {
    asm("ex2.approx.f32 %0, %0;" : "+f"(x));
    return x;
}
__device__ __forceinline__ void mma_f16(float c[4],
                                        uint32_t a0, uint32_t a1, uint32_t a2, uint32_t a3,
                                        uint32_t b0, uint32_t b1) {
    asm volatile(
        "mma.sync.aligned.m16n8k16.row.col.f32.f16.f16.f32 "
        "{%0,%1,%2,%3}, {%4,%5,%6,%7}, {%8,%9}, {%0,%1,%2,%3};"
        : "+f"(c[0]), "+f"(c[1]), "+f"(c[2]), "+f"(c[3])
        : "r"(a0), "r"(a1), "r"(a2), "r"(a3), "r"(b0), "r"(b1));
}
#define LDSM_X4(r0, r1, r2, r3, addr) \
    asm volatile("ldmatrix.sync.aligned.m8n8.x4.shared.b16 {%0,%1,%2,%3}, [%4];" \
                 : "=r"(r0), "=r"(r1), "=r"(r2), "=r"(r3) : "r"(addr))
#define LDSM_X4_T(r0, r1, r2, r3, addr) \
    asm volatile("ldmatrix.sync.aligned.m8n8.x4.trans.shared.b16 {%0,%1,%2,%3}, [%4];" \
                 : "=r"(r0), "=r"(r1), "=r"(r2), "=r"(r3) : "r"(addr))

__device__ __forceinline__ void cp16(void* dst, const void* src) {
    uint32_t d = (uint32_t)__cvta_generic_to_shared(dst);
    asm volatile("cp.async.cg.shared.global [%0], [%1], 16;" :: "r"(d), "l"(src));
}
__device__ __forceinline__ void cp16_z(void* dst, const void* src) {
    uint32_t d = (uint32_t)__cvta_generic_to_shared(dst);
    asm volatile("cp.async.cg.shared.global [%0], [%1], 16, 0;" :: "r"(d), "l"(src));
}
#define CP_COMMIT() asm volatile("cp.async.commit_group;" ::: "memory")
#define CP_WAIT0()  asm volatile("cp.async.wait_group 0;" ::: "memory")

// swizzled byte offset of 16B unit u (0..15) in row t (row stride 256B)
__device__ __forceinline__ uint32_t swz(int t, int u) {
    return (uint32_t)t * ROWB + (uint32_t)((u ^ (t & 7)) << 4);
}

// ---------------------------------------------------------------- RoPE table
__global__ void rope_table_kernel(const int* __restrict__ start_ptr) {
    int idx = blockIdx.x * blockDim.x + threadIdx.x;
    if (idx >= SEQQ * (HD / 2)) return;
    int p = idx & (HD / 2 - 1);
    int si = idx >> 6;
    double pos = (double)(*start_ptr + si);
    double inv = pow(10000.0, -((double)(2 * p)) / (double)HD);
    double s, c;
    sincos(pos * inv, &s, &c);
    g_cos[idx] = (float)c;
    g_sin[idx] = (float)s;
}

// ---------------------------------------------------------------- fresh q/k/v -> fp16
__global__ void qkv_h_kernel(const float* __restrict__ q, const float* __restrict__ k,
                             const float* __restrict__ v) {
    int idx = blockIdx.x * blockDim.x + threadIdx.x;
    const int NU = BATCH * NH * SEQQ * 32;
    if (idx >= 3 * NU) return;
    int which = idx / NU;
    int t = idx - which * NU;
    int j4 = t & 31;
    int si = (t >> 5) & (SEQQ - 1);
    const float* src = (which == 0) ? q : (which == 1) ? k : v;
    float4 x = ((const float4*)src)[t];
    float4 y;
    if (which < 2) {
        int p0 = 2 * j4, p1 = 2 * j4 + 1;
        float c0 = g_cos[si * 64 + p0], s0 = g_sin[si * 64 + p0];
        float c1 = g_cos[si * 64 + p1], s1 = g_sin[si * 64 + p1];
        y.x = x.x * c0 - x.y * s0;
        y.y = x.x * s0 + x.y * c0;
        y.z = x.z * c1 - x.w * s1;
        y.w = x.z * s1 + x.w * c1;
        if (which == 0) {
            // 1/sqrt(128) * log2(e): logits come out pre-scaled for ex2
            const float SC = (float)(0.08838834764831845 * 1.4426950408889634);
            y.x *= SC; y.y *= SC; y.z *= SC; y.w *= SC;
        }
    } else {
        y = x;
    }
    __half* dst = (which == 0) ? g_Qh : (which == 1) ? g_Kh : g_Vh;
    uint2 o;
    o.x = pack_h2(y.x, y.y);
    o.y = pack_h2(y.z, y.w);
    *(uint2*)(dst + 4 * (size_t)t) = o;
}

// ---------------------------------------------------------------- mem_kv prefix -> fp16 head-major
__global__ void mem_h_kernel(const float* __restrict__ mem_kv, const int* __restrict__ start_ptr) {
    int gid = blockIdx.x * blockDim.x + threadIdx.x;
    int uu = gid & 15;
    int r = gid >> 4;
    int t = r & (NMEM - 1);
    int n = (r >> 12) & (NH - 1);
    int b = (r >> 17) & (MAXB - 1);
    int kv = r >> 19;
    if (kv >= 2) return;
    if (t >= *start_ptr) return;
    const float* src = mem_kv + ((((size_t)kv * MAXB + b) * NMEM + t) * NH + n) * HD + uu * 8;
    float4 x0 = *(const float4*)src;
    float4 x1 = *(const float4*)(src + 4);
    uint4 o;
    o.x = pack_h2(x0.x, x0.y);
    o.y = pack_h2(x0.z, x0.w);
    o.z = pack_h2(x1.x, x1.y);
    o.w = pack_h2(x1.z, x1.w);
    __half* dst = (kv == 0) ? g_KmemH : g_VmemH;
    *(uint4*)(dst + ((size_t)(b * NH + n) * NMEM + t) * HD + uu * 8) = o;
}

// ---------------------------------------------------------------- KV tile loader (2-buffer ring)
__device__ __forceinline__ void load_kv_tile(char* sK, char* sV, int buf, int kt,
                                             size_t hb, int start, int T, int tid) {
    int t0 = kt * BK;
    char* dK = sK + buf * (BK * ROWB);
    char* dV = sV + buf * (BK * ROWB);
    const __half* kmemh = g_KmemH + hb * NMEM * HD;
    const __half* vmemh = g_VmemH + hb * NMEM * HD;
    const __half* krh = g_Kh + hb * SEQQ * HD;
    const __half* vrh = g_Vh + hb * SEQQ * HD;
    for (int i = tid; i < BK * 16; i += NTHREADS) {
        int row = i >> 4, u = i & 15, t = t0 + row;
        uint32_t off = swz(row, u);
        if (t < T) {
            const __half* ks = (t < start) ? kmemh + (size_t)t * HD + u * 8
                                           : krh + (size_t)(t - start) * HD + u * 8;
            const __half* vs = (t < start) ? vmemh + (size_t)t * HD + u * 8
                                           : vrh + (size_t)(t - start) * HD + u * 8;
            cp16(dK + off, ks);
            cp16(dV + off, vs);
        } else {
            cp16_z(dK + off, g_KmemH);
            cp16_z(dV + off, g_VmemH);
        }
    }
}

// ---------------------------------------------------------------- fused attention (fp16 mma)
// 2 CTAs/SM: 128-reg budget (Q fragments reloaded from smem each tile), 96KB smem.
__global__ void __launch_bounds__(NTHREADS, 2)
attn_kernel(const int* __restrict__ start_ptr, float* __restrict__ out) {
    const int start = *start_ptr;
    const int T = start + SEQQ;
    const int ntiles = (T + BK - 1) / BK;
    const int qt = blockIdx.x;
    const int head = blockIdx.y;
    const int b = head >> 5;
    const int n = head & (NH - 1);
    const size_t hb = (size_t)b * NH + n;
    const int tid = threadIdx.x;
    const int warp = tid >> 5;
    const int lane = tid & 31;
    const int g = lane >> 2;
    const int c = lane & 3;
    const int l7 = lane & 7;
    const int ts = lane >> 3;

    extern __shared__ char smem[];
    char* sQ = smem;                       // [BQ][256B] swizzled
    char* sK = sQ + BQ * ROWB;             // [2][BK][256B]
    char* sV = sK + 2 * BK * ROWB;         // [2][BK][256B]
    const uint32_t uQ = s2u(sQ), uK = s2u(sK), uV = s2u(sV);

    // ---- prologue: Q + KV tile0 in one group ----
    {
        const __half* qsrc = g_Qh + (hb * SEQQ + (size_t)qt * BQ) * HD;
        for (int i = tid; i < BQ * 16; i += NTHREADS) {
            int row = i >> 4, u = i & 15;
            cp16(sQ + swz(row, u), qsrc + (size_t)row * HD + u * 8);
        }
    }
    load_kv_tile(sK, sV, 0, 0, hb, start, T, tid);
    CP_COMMIT();

    float o[16][4];
#pragma unroll
    for (int i = 0; i < 16; i++)
#pragma unroll
        for (int jj = 0; jj < 4; jj++) o[i][jj] = 0.f;
    float lsum[4] = {0.f, 0.f, 0.f, 0.f};

    const uint32_t qrbase = uQ + (uint32_t)(16 * warp + 8 * (ts & 1) + l7) * ROWB;

    for (int kt = 0; kt < ntiles; kt++) {
        CP_WAIT0();          // tile kt (and everything older) resident
        __syncthreads();     // all warps done with tile kt-1 => its buffer is free

        if (kt + 1 < ntiles) {
            // prefetch kt+1 into the buffer tile kt-1 occupied; overlaps compute below
            load_kv_tile(sK, sV, (kt + 1) & 1, kt + 1, hb, start, T, tid);
            CP_COMMIT();
        }

        const int bufo = (kt & 1) * (BK * ROWB);
        const uint32_t Kb = uK + (uint32_t)bufo;
        const uint32_t Vb = uV + (uint32_t)bufo;

        // ---- S = Q K^T (Q fragments reloaded per pp: 8 transient regs) ----
        float s[8][4];
#pragma unroll
        for (int i = 0; i < 8; i++)
#pragma unroll
            for (int jj = 0; jj < 4; jj++) s[i][jj] = 0.f;

#pragma unroll
        for (int pp = 0; pp < 4; pp++) {
            uint32_t aq[8];
            {
                uint32_t a0 = qrbase + (uint32_t)(((4 * pp + (ts >> 1)) ^ l7) << 4);
                uint32_t a1 = qrbase + (uint32_t)(((4 * pp + 2 + (ts >> 1)) ^ l7) << 4);
                LDSM_X4(aq[0], aq[1], aq[2], aq[3], a0);
                LDSM_X4(aq[4], aq[5], aq[6], aq[7], a1);
            }
            const uint32_t sl = (uint32_t)(((4 * pp + ts) ^ l7) << 4);
#pragma unroll
            for (int nt = 0; nt < 8; nt++) {
                uint32_t addr = Kb + (uint32_t)(8 * nt + l7) * ROWB + sl;
                uint32_t b0, b1, b2, b3;
                LDSM_X4(b0, b1, b2, b3, addr);
                mma_f16(s[nt], aq[0], aq[1], aq[2], aq[3], b0, b1);
                mma_f16(s[nt], aq[4], aq[5], aq[6], aq[7], b2, b3);
            }
        }

        // ---- tail mask (cold: T % BK == 0 for this shape) ----
        const int t0k = kt * BK;
        if (t0k + BK > T) {
#pragma unroll
            for (int nt = 0; nt < 8; nt++) {
                int tc = t0k + nt * 8 + 2 * c;
                if (tc >= T)     { s[nt][0] = -1000.f; s[nt][2] = -1000.f; }
                if (tc + 1 >= T) { s[nt][1] = -1000.f; s[nt][3] = -1000.f; }
            }
        }

        // ---- softmax numerators: bare ex2, pack to fp16 A-frags, ones-mma row sums ----
        uint32_t pa[16];
#pragma unroll
        for (int kk = 0; kk < 4; kk++) {
            uint32_t x0 = pack_h2(ex2f(s[2 * kk][0]),     ex2f(s[2 * kk][1]));
            uint32_t x1 = pack_h2(ex2f(s[2 * kk][2]),     ex2f(s[2 * kk][3]));
            uint32_t x2 = pack_h2(ex2f(s[2 * kk + 1][0]), ex2f(s[2 * kk + 1][1]));
            uint32_t x3 = pack_h2(ex2f(s[2 * kk + 1][2]), ex2f(s[2 * kk + 1][3]));
            pa[4 * kk + 0] = x0;
            pa[4 * kk + 1] = x1;
            pa[4 * kk + 2] = x2;
            pa[4 * kk + 3] = x3;
            mma_f16(lsum, x0, x1, x2, x3, ONES_H2, ONES_H2);
        }

        // ---- O += P V ----
#pragma unroll
        for (int kk = 0; kk < 4; kk++) {
            uint32_t a0 = pa[4 * kk + 0];
            uint32_t a1 = pa[4 * kk + 1];
            uint32_t a2 = pa[4 * kk + 2];
            uint32_t a3 = pa[4 * kk + 3];
            uint32_t rbase = Vb + (uint32_t)(16 * kk + 8 * (ts & 1) + l7) * ROWB;
#pragma unroll
            for (int np = 0; np < 8; np++) {
                uint32_t addr = rbase + (uint32_t)(((2 * np + (ts >> 1)) ^ l7) << 4);
                uint32_t b0, b1, b2, b3;
                LDSM_X4_T(b0, b1, b2, b3, addr);
                mma_f16(o[2 * np], a0, a1, a2, a3, b0, b1);
                mma_f16(o[2 * np + 1], a0, a1, a2, a3, b2, b3);
            }
        }
        // no bottom barrier: next iteration's top barrier precedes any buffer overwrite
    }

    // ---- epilogue: every lane already holds its row sums ----
    float inv0 = 1.f / lsum[0];
    float inv1 = 1.f / lsum[2];

    size_t obase = (hb * SEQQ + (size_t)qt * BQ + warp * 16) * HD;
#pragma unroll
    for (int np = 0; np < 16; np++) {
        float2 w0 = make_float2(o[np][0] * inv0, o[np][1] * inv0);
        float2 w1 = make_float2(o[np][2] * inv1, o[np][3] * inv1);
        *(float2*)(out + obase + (size_t)g * HD + np * 8 + 2 * c) = w0;
        *(float2*)(out + obase + (size_t)(g + 8) * HD + np * 8 + 2 * c) = w1;
    }
}

// ---------------------------------------------------------------------------
extern "C" void kernel_launch(void* const* d_in, const int* in_sizes, int n_in,
                              void* d_out, int out_size) {
    const float* q      = (const float*)d_in[0];
    const float* k      = (const float*)d_in[1];
    const float* v      = (const float*)d_in[2];
    const float* mem_kv = (const float*)d_in[3];
    const int*   start  = (const int*)d_in[4];
    float* out = (float*)d_out;

    rope_table_kernel<<<(SEQQ * (HD / 2) + 255) / 256, 256>>>(start);

    int qkvtot = 3 * BATCH * NH * SEQQ * 32;
    qkv_h_kernel<<<(qkvtot + 255) / 256, 256>>>(q, k, v);

    long mtot = 2L * MAXB * NH * NMEM * 16;
    mem_h_kernel<<<(int)((mtot + 255) / 256), 256>>>(mem_kv, start);

    int smem = (BQ + 4 * BK) * ROWB;  // 32KB Q + 2x16KB K + 2x16KB V = 98304 B
    cudaFuncSetAttribute(attn_kernel, cudaFuncAttributeMaxDynamicSharedMemorySize, smem);
    dim3 grid(SEQQ / BQ, BATCH * NH);
    attn_kernel<<<grid, NTHREADS, smem>>>(start, out);
}